// round 13
// baseline (speedup 1.0000x reference)
#include <cuda_runtime.h>
#include <math.h>

// ---------------- problem constants ----------------
#define B_ 256
#define T_ 512
#define M_ 16
#define C_ 16
#define H_ 768
#define BT_  (B_ * T_)
#define BTM_ (BT_ * M_)
#define BH_  (B_ * H_)

// ---------------- GRU partition ----------------
#define GT_   512                // 16 warps
#define SROWS 36
#define HSL   12
#define RPW   9                  // rows per warp (4 row-groups)
#define STP   68                 // h chunk stride [b][68]

// smem offsets (floats)
#define OFF_WS   0               // [36][768] = 27648
#define OFF_BH   27648           // 40
#define OFF_HPV  27688           // [12][128] = 1536
#define OFF_STA  29224           // 8704
#define OFF_STB  37928           // 8704
#define SM_FLOATS 48456          // partial overlay needs OFF_STA+18432 = 47656

// ---------------- scratch ----------------
__device__ float g_Z[BTM_];
__device__ float g_hill[BTM_];
__device__ float g_xin[BTM_];
__device__ float g_hseq[100859904];          // (T_+1)*B_*H_
__device__ float g_gi[301989888];            // T_*2304*B_  [t][r][b] (incl b_ih)
__device__ unsigned g_arrive;
__device__ unsigned g_release;

// ---------------- helpers ----------------
__device__ __forceinline__ float sigmoidf_(float x) { return 1.0f / (1.0f + expf(-x)); }
__device__ __forceinline__ float softplusf_(float x) {
    return fmaxf(x, 0.0f) + log1pf(expf(-fabsf(x)));
}
__device__ __forceinline__ float wredux(float v) {
#pragma unroll
    for (int off = 16; off; off >>= 1) v += __shfl_xor_sync(0xffffffffu, v, off);
    return v;
}
#define FMA2(acc, a, b) asm("fma.rn.f32x2 %0, %1, %2, %3;" : "=l"(acc) : "l"(a), "l"(b), "l"(acc))
__device__ __forceinline__ float usum_(unsigned long long v) {
    float lo, hi; asm("mov.b64 {%0, %1}, %2;" : "=f"(lo), "=f"(hi) : "l"(v)); return lo + hi;
}
#define CP_ASYNC16(dst, src) \
    asm volatile("cp.async.cg.shared.global [%0], [%1], 16;" :: \
                 "r"((unsigned)__cvta_generic_to_shared(dst)), "l"(src) : "memory")
#define CP_COMMIT()  asm volatile("cp.async.commit_group;" ::: "memory")
#define CP_WAIT0()   asm volatile("cp.async.wait_group 0;" ::: "memory")

// =====================================================================
// kernel 1: causal encoder -> g_Z
// =====================================================================
__global__ void __launch_bounds__(256)
enc_kernel(const float* __restrict__ Xm, const float* __restrict__ A,
           const float* __restrict__ ew1, const float* __restrict__ eb1,
           const float* __restrict__ ew2, const float* __restrict__ eb2,
           const float* __restrict__ nw, const float* __restrict__ nb) {
    __shared__ float sA[256], sw1[512], sw2[256], snw[512];
    __shared__ float sb1[16], sb2[16], snb[16];
    int tid = threadIdx.x;
    sA[tid] = A[tid];
    sw2[tid] = ew2[tid];
    sw1[tid] = ew1[tid];       sw1[tid + 256] = ew1[tid + 256];
    snw[tid] = nw[tid];        snw[tid + 256] = nw[tid + 256];
    if (tid < 16) { sb1[tid] = eb1[tid]; sb2[tid] = eb2[tid]; snb[tid] = nb[tid]; }
    __syncthreads();

    int idx = blockIdx.x * 256 + tid;
    float x[16];
#pragma unroll
    for (int j = 0; j < 16; j++) x[j] = Xm[(size_t)idx * 16 + j];

    float send[16], recv[16];
#pragma unroll
    for (int i = 0; i < 16; i++) {
        float s = 0.f, r = 0.f;
#pragma unroll
        for (int j = 0; j < 16; j++) { s += x[j] * sA[i * 16 + j]; r += x[j] * sA[j * 16 + i]; }
        send[i] = s; recv[i] = r;
    }
    float h1[16];
#pragma unroll
    for (int i = 0; i < 16; i++) {
        float s = sb1[i];
#pragma unroll
        for (int j = 0; j < 16; j++)
            s += send[j] * sw1[i * 32 + j] + recv[j] * sw1[i * 32 + 16 + j];
        h1[i] = fmaxf(s, 0.f);
    }
    float h2[16];
#pragma unroll
    for (int i = 0; i < 16; i++) {
        float s = sb2[i];
#pragma unroll
        for (int j = 0; j < 16; j++) s += h1[j] * sw2[i * 16 + j];
        h2[i] = fmaxf(s, 0.f);
    }
#pragma unroll
    for (int i = 0; i < 16; i++) {
        float s = snb[i];
#pragma unroll
        for (int j = 0; j < 16; j++)
            s += x[j] * snw[i * 32 + j] + h2[j] * snw[i * 32 + 16 + j];
        g_Z[(size_t)idx * 16 + i] = fmaxf(s, 0.f);
    }
}

// =====================================================================
// kernel 2: adstock + hill; g_xin = hill + Z
// =====================================================================
__global__ void __launch_bounds__(256)
adstock_kernel(const float* __restrict__ Xm, const float* __restrict__ alpha,
               const float* __restrict__ hill_a, const float* __restrict__ hill_g) {
    int tid = blockIdx.x * blockDim.x + threadIdx.x;
    int b = tid >> 4, m = tid & 15;
    float a  = fminf(fmaxf(alpha[m], 0.0f), 1.0f);
    float ha = fminf(fmaxf(hill_a[m], 0.1f), 3.0f);
    float hg = fminf(fmaxf(hill_g[m], 0.1f), 2.0f);
    float hga = powf(hg, ha);

    const float* xm = Xm + (size_t)b * T_ * M_ + m;
    float* hil = g_hill + (size_t)b * T_ * M_ + m;
    float* xin = g_xin + (size_t)b * T_ * M_ + m;
    const float* zp = g_Z + (size_t)b * T_ * M_ + m;

    float prev = 0.f, cmax = -1e30f;
    for (int t = 0; t < T_; t++) {
        float cur = xm[t * M_] + a * prev;
        prev = cur;
        hil[t * M_] = cur;
        cmax = fmaxf(cmax, cur);
    }
    cmax = fmaxf(cmax, 1e-6f);
    float inv = 1.0f / cmax;
    for (int t = 0; t < T_; t++) {
        float xn = fmaxf(hil[t * M_] * inv, 0.0f);
        float num = powf(xn, ha);
        float h = num / (num + hga + 1e-8f);
        hil[t * M_] = h;
        xin[t * M_] = h + zp[t * M_];
    }
}

// =====================================================================
// kernel 3: gi precompute. gi[t][r][b] = W_ih[r,:] . x[b,t,:] + b_ih[r]
// grid (T_, 8, 2): t, rchunk(288 rows), bt(128 batches). 256 threads.
// =====================================================================
__global__ void __launch_bounds__(256)
gi_kernel(const float* __restrict__ Xc, const float* __restrict__ W_ih,
          const float* __restrict__ b_ih) {
    __shared__ float Wc[288 * 32];    // 9216
    __shared__ float xt[128 * 36];    // 4608 (stride 36 -> 16B aligned rows)
    __shared__ float bC[288];
    int t = blockIdx.x, rbase = blockIdx.y * 288, b0 = blockIdx.z * 128;
    int tid = threadIdx.x;

    for (int e = tid; e < 288 * 32; e += 256) Wc[e] = W_ih[rbase * 32 + e];
    for (int e = tid; e < 288; e += 256) bC[e] = b_ih[rbase + e];
    for (int e = tid; e < 128 * 32; e += 256) {
        int b = e >> 5, c = e & 31;
        float v = (c < 16) ? g_xin[((size_t)(b0 + b) * T_ + t) * 16 + c]
                           : Xc[((size_t)(b0 + b) * T_ + t) * 16 + (c - 16)];
        xt[b * 36 + c] = v;
    }
    __syncthreads();

    int b = tid & 127;
    int r00 = tid >> 7;               // 0/1; rows r00, r00+2, ...
    const float* xrow = xt + b * 36;
    ulonglong2 x8[8];
#pragma unroll
    for (int i = 0; i < 8; i++) x8[i] = *(const ulonglong2*)(xrow + i * 4);

    float* gout = g_gi + ((size_t)t * 2304 + rbase) * 256 + b0 + b;
    for (int r = r00; r < 288; r += 2) {
        const float* wrow = Wc + r * 32;
        unsigned long long a = 0ull;
#pragma unroll
        for (int i = 0; i < 8; i++) {
            ulonglong2 w8 = *(const ulonglong2*)(wrow + i * 4);
            FMA2(a, w8.x, x8[i].x);
            FMA2(a, w8.y, x8[i].y);
        }
        gout[(size_t)r * 256] = usum_(a) + bC[r];
    }
}

// =====================================================================
// kernel 4: h0 broadcast + barrier reset
// =====================================================================
__global__ void __launch_bounds__(256)
hinit_kernel(const float* __restrict__ h0) {
    int idx = blockIdx.x * 256 + threadIdx.x;
    if (idx == 0) { g_arrive = 0u; g_release = 0u; }
    int j = idx % H_;
    g_hseq[idx] = h0[j];
}

// =====================================================================
// kernel 5: persistent GRU. 128 CTAs = 2 bt x 64 hs. 512 threads =
// 4 row-groups(9 rows) x 4 k-groups(16 cols/chunk each). gi precomputed.
// =====================================================================
extern __shared__ float g_sm[];

__global__ void __launch_bounds__(GT_, 1)
gru_persist_kernel(const float* __restrict__ W_hh, const float* __restrict__ b_hh) {
    float* Ws  = g_sm + OFF_WS;
    float* bh  = g_sm + OFF_BH;
    float* hpv = g_sm + OFF_HPV;
    float* stA = g_sm + OFF_STA;
    float* stB = g_sm + OFF_STB;
    float* Pb  = g_sm + OFF_STA;    // partial overlay: 4 regions of 36*128

    const int tid = threadIdx.x;
    const int tx = tid & 31, wid = tid >> 5;
    const int rg = wid & 3;          // row group 0..3
    const int kg = wid >> 2;         // k group 0..3
    const int r0 = rg * RPW;
    const int bt = blockIdx.x >> 6;
    const int hs = blockIdx.x & 63;
    const int j0 = hs * HSL;
    const int b0 = bt * 128;

    // ---- load W_hh slice + bh ONCE ----
    for (int e = tid; e < SROWS * 768; e += GT_) {
        int r = e / 768, k = e - r * 768;
        int grow = (r < 12) ? (j0 + r) : (r < 24) ? (H_ + j0 + r - 12) : (2 * H_ + j0 + r - 24);
        Ws[e] = W_hh[(size_t)grow * H_ + k];
    }
    if (tid < SROWS) {
        int r = tid;
        int grow = (r < 12) ? (j0 + r) : (r < 24) ? (H_ + j0 + r - 12) : (2 * H_ + j0 + r - 24);
        bh[r] = b_hh[grow];
    }
    // init hprev slice from h0 slot
    for (int e = tid; e < HSL * 128; e += GT_) {
        int j = e >> 7, b = e & 127;
        hpv[e] = g_hseq[(size_t)(b0 + b) * H_ + j0 + j];
    }
    __syncthreads();

    for (int t = 0; t < T_; t++) {
        const float* hp = g_hseq + (size_t)t * BH_;
        float* ho = g_hseq + (size_t)(t + 1) * BH_;

        // ---- stage h chunk 0 -> stA ----
#pragma unroll
        for (int rr = 0; rr < 4; rr++) {
            int i = tid + GT_ * rr;            // < 2048
            int b = i >> 4, kq = i & 15;
            CP_ASYNC16(stA + b * STP + kq * 4, hp + (size_t)(b0 + b) * H_ + kq * 4);
        }
        CP_COMMIT();

        unsigned long long acc[RPW][4];
#pragma unroll
        for (int r = 0; r < RPW; r++)
#pragma unroll
            for (int b = 0; b < 4; b++) acc[r][b] = 0ull;

        for (int c = 0; c < 12; c++) {
            CP_WAIT0();
            __syncthreads();
            float* cur = (c & 1) ? stB : stA;
            float* nxt = (c & 1) ? stA : stB;
            if (c < 11) {
                const float* base = hp + (size_t)b0 * H_ + (c + 1) * 64;
#pragma unroll
                for (int rr = 0; rr < 4; rr++) {
                    int i = tid + GT_ * rr;
                    int b = i >> 4, kq = i & 15;
                    CP_ASYNC16(nxt + b * STP + kq * 4, base + (size_t)b * H_ + kq * 4);
                }
                CP_COMMIT();
            }
            const float* hbase = cur + tx * STP + kg * 16;
            const float* wbase = Ws + r0 * 768 + c * 64 + kg * 16;
#pragma unroll
            for (int k4 = 0; k4 < 16; k4 += 4) {
                ulonglong2 h4[4];
#pragma unroll
                for (int bb = 0; bb < 4; bb++)
                    h4[bb] = *(const ulonglong2*)(hbase + bb * (32 * STP) + k4);
#pragma unroll
                for (int r = 0; r < RPW; r++) {
                    ulonglong2 w4 = *(const ulonglong2*)(wbase + r * 768 + k4);
#pragma unroll
                    for (int bb = 0; bb < 4; bb++) {
                        FMA2(acc[r][bb], w4.x, h4[bb].x);
                        FMA2(acc[r][bb], w4.y, h4[bb].y);
                    }
                }
            }
        }
        __syncthreads();   // all stB reads done before partial overlay writes

        // ---- write split-k partials (region per kg), one sync ----
        float* myP = Pb + kg * 4608;
#pragma unroll
        for (int r = 0; r < RPW; r++)
#pragma unroll
            for (int bb = 0; bb < 4; bb++)
                myP[(r0 + r) * 128 + tx + 32 * bb] = usum_(acc[r][bb]);
        __syncthreads();

        // ---- epilogue: gates + state update ----
        const float* gi_t = g_gi + (size_t)t * 2304 * 256;
        for (int e = tid; e < HSL * 128; e += GT_) {
            int j = e >> 7, b = e & 127;
            int o = j * 128 + b;
            float hr = Pb[o] + Pb[4608 + o] + Pb[9216 + o] + Pb[13824 + o];
            int oz = (12 + j) * 128 + b;
            float hz = Pb[oz] + Pb[4608 + oz] + Pb[9216 + oz] + Pb[13824 + oz];
            int on = (24 + j) * 128 + b;
            float hn = Pb[on] + Pb[4608 + on] + Pb[9216 + on] + Pb[13824 + on];
            float gr = gi_t[(size_t)(j0 + j) * 256 + b0 + b];
            float gz = gi_t[(size_t)(768 + j0 + j) * 256 + b0 + b];
            float gn = gi_t[(size_t)(1536 + j0 + j) * 256 + b0 + b];
            float rg_ = sigmoidf_(gr + hr + bh[j]);
            float zg  = sigmoidf_(gz + hz + bh[12 + j]);
            float nn  = tanhf(gn + rg_ * (hn + bh[24 + j]));
            float hv  = hpv[e];
            float hnew = (1.f - zg) * nn + zg * hv;
            hpv[e] = hnew;
            ho[(size_t)(b0 + b) * H_ + j0 + j] = hnew;
        }

        // ---- grid barrier ----
        if (t < T_ - 1) {
            __threadfence();
            __syncthreads();
            if (tid == 0) {
                unsigned tgt = (unsigned)t + 1u;
                if (atomicAdd(&g_arrive, 1u) == 127u) {
                    g_arrive = 0u;
                    __threadfence();
                    *(volatile unsigned*)&g_release = tgt;
                } else {
                    while (*(volatile unsigned*)&g_release < tgt) { __nanosleep(32); }
                }
                __threadfence();
            }
            __syncthreads();
        }
    }
}

// =====================================================================
// kernel 6: heads
// =====================================================================
__global__ void __launch_bounds__(256, 1)
heads_kernel(const float* __restrict__ Xc,
             const float* __restrict__ wraw_w, const float* __restrict__ wraw_b,
             const float* __restrict__ ctrl_w, const float* __restrict__ ctrl_b,
             const float* __restrict__ reg_emb, const float* __restrict__ bias,
             float* __restrict__ out_y, float* __restrict__ out_w, float* __restrict__ out_c) {
    extern __shared__ float hsm[];
    float* sww = hsm;
    float* scw = sww + 12288;
    float* scb = scw + 12288;
    float* srg = scb + 768;
    float* swb = srg + 768;
    int tid = threadIdx.x;
    for (int e = tid; e < 12288; e += 256) { sww[e] = wraw_w[e]; scw[e] = ctrl_w[e]; }
    for (int e = tid; e < 768; e += 256) { scb[e] = ctrl_b[e]; srg[e] = reg_emb[e]; }
    if (tid < 16) swb[tid] = wraw_b[tid];
    __syncthreads();

    int wid = tid >> 5, lane = tid & 31;
    float bias0 = bias[0];

    float rp = 0.f;
#pragma unroll
    for (int i = 0; i < 24; i++) rp += srg[lane + 32 * i];
    rp = wredux(rp) * 0.3f;

    for (int it = 0; it < 8; it++) {
        int n = blockIdx.x * 64 + wid * 8 + it;
        int b = n >> 9, t = n & 511;

        const float* hrow = g_hseq + (size_t)(t + 1) * BH_ + (size_t)b * H_;
        float hv[24];
#pragma unroll
        for (int i = 0; i < 24; i++) hv[i] = hrow[lane + 32 * i];
        float wp[16];
#pragma unroll
        for (int m = 0; m < 16; m++) {
            float p = 0.f;
#pragma unroll
            for (int i = 0; i < 24; i++) p += hv[i] * sww[m * 768 + lane + 32 * i];
            p = wredux(p);
            wp[m] = softplusf_(p + swb[m]);
        }
        if (t == 0) {
            const float* h2 = g_hseq + (size_t)2 * BH_ + (size_t)b * H_;
            float h2v[24];
#pragma unroll
            for (int i = 0; i < 24; i++) h2v[i] = h2[lane + 32 * i];
#pragma unroll
            for (int m = 0; m < 16; m++) {
                float p = 0.f;
#pragma unroll
                for (int i = 0; i < 24; i++) p += h2v[i] * sww[m * 768 + lane + 32 * i];
                p = wredux(p);
                wp[m] = 0.5f * softplusf_(p + swb[m]) + 0.5f * wp[m];
            }
        }

        float media = 0.f;
        const float* hillrow = g_hill + ((size_t)b * T_ + t) * M_;
        float cb[16];
#pragma unroll
        for (int m = 0; m < 16; m++) { cb[m] = hillrow[m] * wp[m]; media += cb[m]; }

        float xc[16];
#pragma unroll
        for (int c = 0; c < 16; c++) xc[c] = Xc[((size_t)b * T_ + t) * C_ + c];
        float ct = 0.f;
#pragma unroll
        for (int i = 0; i < 24; i++) {
            int j = lane + 32 * i;
            float s = scb[j];
#pragma unroll
            for (int c = 0; c < 16; c++) s += xc[c] * scw[j * 16 + c];
            ct += fmaxf(s, 0.f);
        }
        ct = wredux(ct) * 0.3f;

        float y = media + ct + rp + bias0;
        if (lane == 0) out_y[(size_t)b * T_ + t] = y;
        if (out_w && lane < 16) out_w[((size_t)b * T_ + t) * M_ + lane] = wp[lane];
        if (out_c && lane < 16) out_c[((size_t)b * T_ + t) * M_ + lane] = cb[lane];
    }
}

// =====================================================================
// launch
// =====================================================================
extern "C" void kernel_launch(void* const* d_in, const int* in_sizes, int n_in,
                              void* d_out, int out_size) {
    const float* Xm     = (const float*)d_in[0];
    const float* Xc     = (const float*)d_in[1];
    const float* A      = (const float*)d_in[3];
    const float* ew1    = (const float*)d_in[4];
    const float* eb1    = (const float*)d_in[5];
    const float* ew2    = (const float*)d_in[6];
    const float* eb2    = (const float*)d_in[7];
    const float* nw     = (const float*)d_in[8];
    const float* nb     = (const float*)d_in[9];
    const float* W_ih   = (const float*)d_in[10];
    const float* W_hh   = (const float*)d_in[11];
    const float* b_ih   = (const float*)d_in[12];
    const float* b_hh   = (const float*)d_in[13];
    const float* wraw_w = (const float*)d_in[14];
    const float* wraw_b = (const float*)d_in[15];
    const float* alpha  = (const float*)d_in[16];
    const float* hill_a = (const float*)d_in[17];
    const float* hill_g = (const float*)d_in[18];
    const float* ctrl_w = (const float*)d_in[19];
    const float* ctrl_b = (const float*)d_in[20];
    const float* regemb = (const float*)d_in[21];
    const float* bias   = (const float*)d_in[22];
    const float* h0     = (const float*)d_in[23];

    const int GRU_SMEM  = SM_FLOATS * 4;                                 // 193824
    const int HEAD_SMEM = (12288 + 12288 + 768 + 768 + 16) * 4;          // 104512
    cudaFuncSetAttribute(gru_persist_kernel, cudaFuncAttributeMaxDynamicSharedMemorySize, GRU_SMEM);
    cudaFuncSetAttribute(heads_kernel, cudaFuncAttributeMaxDynamicSharedMemorySize, HEAD_SMEM);

    enc_kernel<<<BT_ / 256, 256>>>(Xm, A, ew1, eb1, ew2, eb2, nw, nb);
    adstock_kernel<<<(B_ * M_) / 256, 256>>>(Xm, alpha, hill_a, hill_g);
    gi_kernel<<<dim3(T_, 8, 2), 256>>>(Xc, W_ih, b_ih);
    hinit_kernel<<<BH_ / 256, 256>>>(h0);

    gru_persist_kernel<<<128, GT_, GRU_SMEM>>>(W_hh, b_hh);

    float* out = (float*)d_out;
    float* oy = out;
    float* ow = nullptr;
    float* oc = nullptr;
    if (out_size >= BT_ + 2 * BTM_) { ow = out + BT_; oc = out + BT_ + BTM_; }
    else if (out_size >= BT_ + BTM_) { ow = out + BT_; }

    heads_kernel<<<BT_ / 64, 256, HEAD_SMEM>>>(Xc, wraw_w, wraw_b, ctrl_w, ctrl_b,
                                               regemb, bias, oy, ow, oc);
}

// round 14
// speedup vs baseline: 1.0015x; 1.0015x over previous
#include <cuda_runtime.h>
#include <math.h>

// ---------------- problem constants ----------------
#define B_ 256
#define T_ 512
#define M_ 16
#define C_ 16
#define H_ 768
#define BT_  (B_ * T_)
#define BTM_ (BT_ * M_)
#define BH_  (B_ * H_)

// ---------------- GRU partition ----------------
#define GT_   512                // 16 warps
#define SROWS 36
#define HSL   12
#define RPW   9                  // rows per warp (4 row-groups)
#define STP   68                 // h chunk stride [b][68]

// smem offsets (floats)
#define OFF_WS   0               // [36][768] = 27648
#define OFF_BH   27648           // 40
#define OFF_HPV  27688           // [12][128] = 1536
#define OFF_STA  29224           // 8704
#define OFF_STB  37928           // 8704
#define SM_FLOATS 48456          // partial overlay needs OFF_STA+18432 = 47656

// ---------------- scratch ----------------
__device__ float g_Z[BTM_];
__device__ float g_hill[BTM_];
__device__ float g_xin[BTM_];
__device__ float g_hseq[100859904];          // (T_+1)*B_*H_
__device__ float g_gi[301989888];            // T_*2304*B_  [t][r][b] (incl b_ih)
__device__ unsigned g_arrive;
__device__ unsigned g_release;

// ---------------- helpers ----------------
__device__ __forceinline__ float sigmoidf_(float x) { return 1.0f / (1.0f + expf(-x)); }
__device__ __forceinline__ float softplusf_(float x) {
    return fmaxf(x, 0.0f) + log1pf(expf(-fabsf(x)));
}
__device__ __forceinline__ float wredux(float v) {
#pragma unroll
    for (int off = 16; off; off >>= 1) v += __shfl_xor_sync(0xffffffffu, v, off);
    return v;
}
#define FMA2(acc, a, b) asm("fma.rn.f32x2 %0, %1, %2, %3;" : "=l"(acc) : "l"(a), "l"(b), "l"(acc))
__device__ __forceinline__ float usum_(unsigned long long v) {
    float lo, hi; asm("mov.b64 {%0, %1}, %2;" : "=f"(lo), "=f"(hi) : "l"(v)); return lo + hi;
}
#define CP_ASYNC16(dst, src) \
    asm volatile("cp.async.cg.shared.global [%0], [%1], 16;" :: \
                 "r"((unsigned)__cvta_generic_to_shared(dst)), "l"(src) : "memory")
#define CP_COMMIT()  asm volatile("cp.async.commit_group;" ::: "memory")
#define CP_WAIT0()   asm volatile("cp.async.wait_group 0;" ::: "memory")

// =====================================================================
// kernel 1: causal encoder -> g_Z
// =====================================================================
__global__ void __launch_bounds__(256)
enc_kernel(const float* __restrict__ Xm, const float* __restrict__ A,
           const float* __restrict__ ew1, const float* __restrict__ eb1,
           const float* __restrict__ ew2, const float* __restrict__ eb2,
           const float* __restrict__ nw, const float* __restrict__ nb) {
    __shared__ float sA[256], sw1[512], sw2[256], snw[512];
    __shared__ float sb1[16], sb2[16], snb[16];
    int tid = threadIdx.x;
    sA[tid] = A[tid];
    sw2[tid] = ew2[tid];
    sw1[tid] = ew1[tid];       sw1[tid + 256] = ew1[tid + 256];
    snw[tid] = nw[tid];        snw[tid + 256] = nw[tid + 256];
    if (tid < 16) { sb1[tid] = eb1[tid]; sb2[tid] = eb2[tid]; snb[tid] = nb[tid]; }
    __syncthreads();

    int idx = blockIdx.x * 256 + tid;
    float x[16];
#pragma unroll
    for (int j = 0; j < 16; j++) x[j] = Xm[(size_t)idx * 16 + j];

    float send[16], recv[16];
#pragma unroll
    for (int i = 0; i < 16; i++) {
        float s = 0.f, r = 0.f;
#pragma unroll
        for (int j = 0; j < 16; j++) { s += x[j] * sA[i * 16 + j]; r += x[j] * sA[j * 16 + i]; }
        send[i] = s; recv[i] = r;
    }
    float h1[16];
#pragma unroll
    for (int i = 0; i < 16; i++) {
        float s = sb1[i];
#pragma unroll
        for (int j = 0; j < 16; j++)
            s += send[j] * sw1[i * 32 + j] + recv[j] * sw1[i * 32 + 16 + j];
        h1[i] = fmaxf(s, 0.f);
    }
    float h2[16];
#pragma unroll
    for (int i = 0; i < 16; i++) {
        float s = sb2[i];
#pragma unroll
        for (int j = 0; j < 16; j++) s += h1[j] * sw2[i * 16 + j];
        h2[i] = fmaxf(s, 0.f);
    }
#pragma unroll
    for (int i = 0; i < 16; i++) {
        float s = snb[i];
#pragma unroll
        for (int j = 0; j < 16; j++)
            s += x[j] * snw[i * 32 + j] + h2[j] * snw[i * 32 + 16 + j];
        g_Z[(size_t)idx * 16 + i] = fmaxf(s, 0.f);
    }
}

// =====================================================================
// kernel 2: adstock + hill; g_xin = hill + Z
// =====================================================================
__global__ void __launch_bounds__(256)
adstock_kernel(const float* __restrict__ Xm, const float* __restrict__ alpha,
               const float* __restrict__ hill_a, const float* __restrict__ hill_g) {
    int tid = blockIdx.x * blockDim.x + threadIdx.x;
    int b = tid >> 4, m = tid & 15;
    float a  = fminf(fmaxf(alpha[m], 0.0f), 1.0f);
    float ha = fminf(fmaxf(hill_a[m], 0.1f), 3.0f);
    float hg = fminf(fmaxf(hill_g[m], 0.1f), 2.0f);
    float hga = powf(hg, ha);

    const float* xm = Xm + (size_t)b * T_ * M_ + m;
    float* hil = g_hill + (size_t)b * T_ * M_ + m;
    float* xin = g_xin + (size_t)b * T_ * M_ + m;
    const float* zp = g_Z + (size_t)b * T_ * M_ + m;

    float prev = 0.f, cmax = -1e30f;
    for (int t = 0; t < T_; t++) {
        float cur = xm[t * M_] + a * prev;
        prev = cur;
        hil[t * M_] = cur;
        cmax = fmaxf(cmax, cur);
    }
    cmax = fmaxf(cmax, 1e-6f);
    float inv = 1.0f / cmax;
    for (int t = 0; t < T_; t++) {
        float xn = fmaxf(hil[t * M_] * inv, 0.0f);
        float num = powf(xn, ha);
        float h = num / (num + hga + 1e-8f);
        hil[t * M_] = h;
        xin[t * M_] = h + zp[t * M_];
    }
}

// =====================================================================
// kernel 3: gi precompute. gi[t][r][b] = W_ih[r,:] . x[b,t,:] + b_ih[r]
// grid (T_, 8, 2): t, rchunk(288 rows), bt(128 batches). 256 threads.
// =====================================================================
__global__ void __launch_bounds__(256)
gi_kernel(const float* __restrict__ Xc, const float* __restrict__ W_ih,
          const float* __restrict__ b_ih) {
    __shared__ float Wc[288 * 32];    // 9216
    __shared__ float xt[128 * 36];    // 4608 (stride 36 -> 16B aligned rows)
    __shared__ float bC[288];
    int t = blockIdx.x, rbase = blockIdx.y * 288, b0 = blockIdx.z * 128;
    int tid = threadIdx.x;

    for (int e = tid; e < 288 * 32; e += 256) Wc[e] = W_ih[rbase * 32 + e];
    for (int e = tid; e < 288; e += 256) bC[e] = b_ih[rbase + e];
    for (int e = tid; e < 128 * 32; e += 256) {
        int b = e >> 5, c = e & 31;
        float v = (c < 16) ? g_xin[((size_t)(b0 + b) * T_ + t) * 16 + c]
                           : Xc[((size_t)(b0 + b) * T_ + t) * 16 + (c - 16)];
        xt[b * 36 + c] = v;
    }
    __syncthreads();

    int b = tid & 127;
    int r00 = tid >> 7;               // 0/1; rows r00, r00+2, ...
    const float* xrow = xt + b * 36;
    ulonglong2 x8[8];
#pragma unroll
    for (int i = 0; i < 8; i++) x8[i] = *(const ulonglong2*)(xrow + i * 4);

    float* gout = g_gi + ((size_t)t * 2304 + rbase) * 256 + b0 + b;
    for (int r = r00; r < 288; r += 2) {
        const float* wrow = Wc + r * 32;
        unsigned long long a = 0ull;
#pragma unroll
        for (int i = 0; i < 8; i++) {
            ulonglong2 w8 = *(const ulonglong2*)(wrow + i * 4);
            FMA2(a, w8.x, x8[i].x);
            FMA2(a, w8.y, x8[i].y);
        }
        gout[(size_t)r * 256] = usum_(a) + bC[r];
    }
}

// =====================================================================
// kernel 4: h0 broadcast + barrier reset
// =====================================================================
__global__ void __launch_bounds__(256)
hinit_kernel(const float* __restrict__ h0) {
    int idx = blockIdx.x * 256 + threadIdx.x;
    if (idx == 0) { g_arrive = 0u; g_release = 0u; }
    int j = idx % H_;
    g_hseq[idx] = h0[j];
}

// =====================================================================
// kernel 5: persistent GRU. 128 CTAs = 2 bt x 64 hs. 512 threads =
// 4 row-groups(9 rows) x 4 k-groups(16 cols/chunk each). gi precomputed.
// =====================================================================
extern __shared__ float g_sm[];

__global__ void __launch_bounds__(GT_, 1)
gru_persist_kernel(const float* __restrict__ W_hh, const float* __restrict__ b_hh) {
    float* Ws  = g_sm + OFF_WS;
    float* bh  = g_sm + OFF_BH;
    float* hpv = g_sm + OFF_HPV;
    float* stA = g_sm + OFF_STA;
    float* stB = g_sm + OFF_STB;
    float* Pb  = g_sm + OFF_STA;    // partial overlay: 4 regions of 36*128

    const int tid = threadIdx.x;
    const int tx = tid & 31, wid = tid >> 5;
    const int rg = wid & 3;          // row group 0..3
    const int kg = wid >> 2;         // k group 0..3
    const int r0 = rg * RPW;
    const int bt = blockIdx.x >> 6;
    const int hs = blockIdx.x & 63;
    const int j0 = hs * HSL;
    const int b0 = bt * 128;

    // ---- load W_hh slice + bh ONCE ----
    for (int e = tid; e < SROWS * 768; e += GT_) {
        int r = e / 768, k = e - r * 768;
        int grow = (r < 12) ? (j0 + r) : (r < 24) ? (H_ + j0 + r - 12) : (2 * H_ + j0 + r - 24);
        Ws[e] = W_hh[(size_t)grow * H_ + k];
    }
    if (tid < SROWS) {
        int r = tid;
        int grow = (r < 12) ? (j0 + r) : (r < 24) ? (H_ + j0 + r - 12) : (2 * H_ + j0 + r - 24);
        bh[r] = b_hh[grow];
    }
    // init hprev slice from h0 slot
    for (int e = tid; e < HSL * 128; e += GT_) {
        int j = e >> 7, b = e & 127;
        hpv[e] = g_hseq[(size_t)(b0 + b) * H_ + j0 + j];
    }
    __syncthreads();

    for (int t = 0; t < T_; t++) {
        const float* hp = g_hseq + (size_t)t * BH_;
        float* ho = g_hseq + (size_t)(t + 1) * BH_;

        // ---- stage h chunk 0 -> stA ----
#pragma unroll
        for (int rr = 0; rr < 4; rr++) {
            int i = tid + GT_ * rr;            // < 2048
            int b = i >> 4, kq = i & 15;
            CP_ASYNC16(stA + b * STP + kq * 4, hp + (size_t)(b0 + b) * H_ + kq * 4);
        }
        CP_COMMIT();

        unsigned long long acc[RPW][4];
#pragma unroll
        for (int r = 0; r < RPW; r++)
#pragma unroll
            for (int b = 0; b < 4; b++) acc[r][b] = 0ull;

        for (int c = 0; c < 12; c++) {
            CP_WAIT0();
            __syncthreads();
            float* cur = (c & 1) ? stB : stA;
            float* nxt = (c & 1) ? stA : stB;
            if (c < 11) {
                const float* base = hp + (size_t)b0 * H_ + (c + 1) * 64;
#pragma unroll
                for (int rr = 0; rr < 4; rr++) {
                    int i = tid + GT_ * rr;
                    int b = i >> 4, kq = i & 15;
                    CP_ASYNC16(nxt + b * STP + kq * 4, base + (size_t)b * H_ + kq * 4);
                }
                CP_COMMIT();
            }
            const float* hbase = cur + tx * STP + kg * 16;
            const float* wbase = Ws + r0 * 768 + c * 64 + kg * 16;
#pragma unroll
            for (int k4 = 0; k4 < 16; k4 += 4) {
                ulonglong2 h4[4];
#pragma unroll
                for (int bb = 0; bb < 4; bb++)
                    h4[bb] = *(const ulonglong2*)(hbase + bb * (32 * STP) + k4);
#pragma unroll
                for (int r = 0; r < RPW; r++) {
                    ulonglong2 w4 = *(const ulonglong2*)(wbase + r * 768 + k4);
#pragma unroll
                    for (int bb = 0; bb < 4; bb++) {
                        FMA2(acc[r][bb], w4.x, h4[bb].x);
                        FMA2(acc[r][bb], w4.y, h4[bb].y);
                    }
                }
            }
        }
        __syncthreads();   // all stB reads done before partial overlay writes

        // ---- write split-k partials (region per kg), one sync ----
        float* myP = Pb + kg * 4608;
#pragma unroll
        for (int r = 0; r < RPW; r++)
#pragma unroll
            for (int bb = 0; bb < 4; bb++)
                myP[(r0 + r) * 128 + tx + 32 * bb] = usum_(acc[r][bb]);
        __syncthreads();

        // ---- epilogue: gates + state update ----
        const float* gi_t = g_gi + (size_t)t * 2304 * 256;
        for (int e = tid; e < HSL * 128; e += GT_) {
            int j = e >> 7, b = e & 127;
            int o = j * 128 + b;
            float hr = Pb[o] + Pb[4608 + o] + Pb[9216 + o] + Pb[13824 + o];
            int oz = (12 + j) * 128 + b;
            float hz = Pb[oz] + Pb[4608 + oz] + Pb[9216 + oz] + Pb[13824 + oz];
            int on = (24 + j) * 128 + b;
            float hn = Pb[on] + Pb[4608 + on] + Pb[9216 + on] + Pb[13824 + on];
            float gr = gi_t[(size_t)(j0 + j) * 256 + b0 + b];
            float gz = gi_t[(size_t)(768 + j0 + j) * 256 + b0 + b];
            float gn = gi_t[(size_t)(1536 + j0 + j) * 256 + b0 + b];
            float rg_ = sigmoidf_(gr + hr + bh[j]);
            float zg  = sigmoidf_(gz + hz + bh[12 + j]);
            float nn  = tanhf(gn + rg_ * (hn + bh[24 + j]));
            float hv  = hpv[e];
            float hnew = (1.f - zg) * nn + zg * hv;
            hpv[e] = hnew;
            ho[(size_t)(b0 + b) * H_ + j0 + j] = hnew;
        }

        // ---- grid barrier ----
        if (t < T_ - 1) {
            __threadfence();
            __syncthreads();
            if (tid == 0) {
                unsigned tgt = (unsigned)t + 1u;
                if (atomicAdd(&g_arrive, 1u) == 127u) {
                    g_arrive = 0u;
                    __threadfence();
                    *(volatile unsigned*)&g_release = tgt;
                } else {
                    while (*(volatile unsigned*)&g_release < tgt) { __nanosleep(32); }
                }
                __threadfence();
            }
            __syncthreads();
        }
    }
}

// =====================================================================
// kernel 6: heads
// =====================================================================
__global__ void __launch_bounds__(256, 1)
heads_kernel(const float* __restrict__ Xc,
             const float* __restrict__ wraw_w, const float* __restrict__ wraw_b,
             const float* __restrict__ ctrl_w, const float* __restrict__ ctrl_b,
             const float* __restrict__ reg_emb, const float* __restrict__ bias,
             float* __restrict__ out_y, float* __restrict__ out_w, float* __restrict__ out_c) {
    extern __shared__ float hsm[];
    float* sww = hsm;
    float* scw = sww + 12288;
    float* scb = scw + 12288;
    float* srg = scb + 768;
    float* swb = srg + 768;
    int tid = threadIdx.x;
    for (int e = tid; e < 12288; e += 256) { sww[e] = wraw_w[e]; scw[e] = ctrl_w[e]; }
    for (int e = tid; e < 768; e += 256) { scb[e] = ctrl_b[e]; srg[e] = reg_emb[e]; }
    if (tid < 16) swb[tid] = wraw_b[tid];
    __syncthreads();

    int wid = tid >> 5, lane = tid & 31;
    float bias0 = bias[0];

    float rp = 0.f;
#pragma unroll
    for (int i = 0; i < 24; i++) rp += srg[lane + 32 * i];
    rp = wredux(rp) * 0.3f;

    for (int it = 0; it < 8; it++) {
        int n = blockIdx.x * 64 + wid * 8 + it;
        int b = n >> 9, t = n & 511;

        const float* hrow = g_hseq + (size_t)(t + 1) * BH_ + (size_t)b * H_;
        float hv[24];
#pragma unroll
        for (int i = 0; i < 24; i++) hv[i] = hrow[lane + 32 * i];
        float wp[16];
#pragma unroll
        for (int m = 0; m < 16; m++) {
            float p = 0.f;
#pragma unroll
            for (int i = 0; i < 24; i++) p += hv[i] * sww[m * 768 + lane + 32 * i];
            p = wredux(p);
            wp[m] = softplusf_(p + swb[m]);
        }
        if (t == 0) {
            const float* h2 = g_hseq + (size_t)2 * BH_ + (size_t)b * H_;
            float h2v[24];
#pragma unroll
            for (int i = 0; i < 24; i++) h2v[i] = h2[lane + 32 * i];
#pragma unroll
            for (int m = 0; m < 16; m++) {
                float p = 0.f;
#pragma unroll
                for (int i = 0; i < 24; i++) p += h2v[i] * sww[m * 768 + lane + 32 * i];
                p = wredux(p);
                wp[m] = 0.5f * softplusf_(p + swb[m]) + 0.5f * wp[m];
            }
        }

        float media = 0.f;
        const float* hillrow = g_hill + ((size_t)b * T_ + t) * M_;
        float cb[16];
#pragma unroll
        for (int m = 0; m < 16; m++) { cb[m] = hillrow[m] * wp[m]; media += cb[m]; }

        float xc[16];
#pragma unroll
        for (int c = 0; c < 16; c++) xc[c] = Xc[((size_t)b * T_ + t) * C_ + c];
        float ct = 0.f;
#pragma unroll
        for (int i = 0; i < 24; i++) {
            int j = lane + 32 * i;
            float s = scb[j];
#pragma unroll
            for (int c = 0; c < 16; c++) s += xc[c] * scw[j * 16 + c];
            ct += fmaxf(s, 0.f);
        }
        ct = wredux(ct) * 0.3f;

        float y = media + ct + rp + bias0;
        if (lane == 0) out_y[(size_t)b * T_ + t] = y;
        if (out_w && lane < 16) out_w[((size_t)b * T_ + t) * M_ + lane] = wp[lane];
        if (out_c && lane < 16) out_c[((size_t)b * T_ + t) * M_ + lane] = cb[lane];
    }
}

// =====================================================================
// launch
// =====================================================================
extern "C" void kernel_launch(void* const* d_in, const int* in_sizes, int n_in,
                              void* d_out, int out_size) {
    const float* Xm     = (const float*)d_in[0];
    const float* Xc     = (const float*)d_in[1];
    const float* A      = (const float*)d_in[3];
    const float* ew1    = (const float*)d_in[4];
    const float* eb1    = (const float*)d_in[5];
    const float* ew2    = (const float*)d_in[6];
    const float* eb2    = (const float*)d_in[7];
    const float* nw     = (const float*)d_in[8];
    const float* nb     = (const float*)d_in[9];
    const float* W_ih   = (const float*)d_in[10];
    const float* W_hh   = (const float*)d_in[11];
    const float* b_ih   = (const float*)d_in[12];
    const float* b_hh   = (const float*)d_in[13];
    const float* wraw_w = (const float*)d_in[14];
    const float* wraw_b = (const float*)d_in[15];
    const float* alpha  = (const float*)d_in[16];
    const float* hill_a = (const float*)d_in[17];
    const float* hill_g = (const float*)d_in[18];
    const float* ctrl_w = (const float*)d_in[19];
    const float* ctrl_b = (const float*)d_in[20];
    const float* regemb = (const float*)d_in[21];
    const float* bias   = (const float*)d_in[22];
    const float* h0     = (const float*)d_in[23];

    const int GRU_SMEM  = SM_FLOATS * 4;                                 // 193824
    const int HEAD_SMEM = (12288 + 12288 + 768 + 768 + 16) * 4;          // 104512
    cudaFuncSetAttribute(gru_persist_kernel, cudaFuncAttributeMaxDynamicSharedMemorySize, GRU_SMEM);
    cudaFuncSetAttribute(heads_kernel, cudaFuncAttributeMaxDynamicSharedMemorySize, HEAD_SMEM);

    enc_kernel<<<BT_ / 256, 256>>>(Xm, A, ew1, eb1, ew2, eb2, nw, nb);
    adstock_kernel<<<(B_ * M_) / 256, 256>>>(Xm, alpha, hill_a, hill_g);
    gi_kernel<<<dim3(T_, 8, 2), 256>>>(Xc, W_ih, b_ih);
    hinit_kernel<<<BH_ / 256, 256>>>(h0);

    gru_persist_kernel<<<128, GT_, GRU_SMEM>>>(W_hh, b_hh);

    float* out = (float*)d_out;
    float* oy = out;
    float* ow = nullptr;
    float* oc = nullptr;
    if (out_size >= BT_ + 2 * BTM_) { ow = out + BT_; oc = out + BT_ + BTM_; }
    else if (out_size >= BT_ + BTM_) { ow = out + BT_; }

    heads_kernel<<<BT_ / 64, 256, HEAD_SMEM>>>(Xc, wraw_w, wraw_b, ctrl_w, ctrl_b,
                                               regemb, bias, oy, ow, oc);
}

// round 15
// speedup vs baseline: 1.0266x; 1.0250x over previous
#include <cuda_runtime.h>
#include <math.h>

// ---------------- problem constants ----------------
#define B_ 256
#define T_ 512
#define M_ 16
#define C_ 16
#define H_ 768
#define BT_  (B_ * T_)
#define BTM_ (BT_ * M_)
#define BH_  (B_ * H_)

// ---------------- GRU partition ----------------
#define GT_   384                // 12 warps = 6 row-groups x 2 k-groups
#define SROWS 36
#define HSL   12
#define RPW   6                  // rows per warp
#define STP   68                 // h chunk stride [b][68]

// smem offsets (floats)
#define OFF_WS   0               // [36][768] = 27648
#define OFF_BH   27648           // 40
#define OFF_HPV  27688           // [12][128] = 1536
#define OFF_STA  29224           // 8704
#define OFF_STB  37928           // 8704
#define SM_FLOATS 46632          // 186528 bytes

// ---------------- scratch ----------------
__device__ float g_Z[BTM_];
__device__ float g_hill[BTM_];
__device__ float g_xin[BTM_];
__device__ float g_hseq[100859904];          // (T_+1)*B_*H_
__device__ float g_gi[301989888];            // [t][r][b] incl b_ih
__device__ unsigned g_arrive;
__device__ unsigned g_release;

// ---------------- helpers ----------------
__device__ __forceinline__ float sigmoidf_(float x) { return 1.0f / (1.0f + expf(-x)); }
__device__ __forceinline__ float softplusf_(float x) {
    return fmaxf(x, 0.0f) + log1pf(expf(-fabsf(x)));
}
__device__ __forceinline__ float wredux(float v) {
#pragma unroll
    for (int off = 16; off; off >>= 1) v += __shfl_xor_sync(0xffffffffu, v, off);
    return v;
}
#define FMA2(acc, a, b) asm("fma.rn.f32x2 %0, %1, %2, %3;" : "=l"(acc) : "l"(a), "l"(b), "l"(acc))
__device__ __forceinline__ float usum_(unsigned long long v) {
    float lo, hi; asm("mov.b64 {%0, %1}, %2;" : "=f"(lo), "=f"(hi) : "l"(v)); return lo + hi;
}
#define CP_ASYNC16(dst, src) \
    asm volatile("cp.async.cg.shared.global [%0], [%1], 16;" :: \
                 "r"((unsigned)__cvta_generic_to_shared(dst)), "l"(src) : "memory")
#define CP_COMMIT()  asm volatile("cp.async.commit_group;" ::: "memory")
#define CP_WAIT0()   asm volatile("cp.async.wait_group 0;" ::: "memory")

// =====================================================================
// kernel 1: causal encoder -> g_Z
// =====================================================================
__global__ void __launch_bounds__(256)
enc_kernel(const float* __restrict__ Xm, const float* __restrict__ A,
           const float* __restrict__ ew1, const float* __restrict__ eb1,
           const float* __restrict__ ew2, const float* __restrict__ eb2,
           const float* __restrict__ nw, const float* __restrict__ nb) {
    __shared__ float sA[256], sw1[512], sw2[256], snw[512];
    __shared__ float sb1[16], sb2[16], snb[16];
    int tid = threadIdx.x;
    sA[tid] = A[tid];
    sw2[tid] = ew2[tid];
    sw1[tid] = ew1[tid];       sw1[tid + 256] = ew1[tid + 256];
    snw[tid] = nw[tid];        snw[tid + 256] = nw[tid + 256];
    if (tid < 16) { sb1[tid] = eb1[tid]; sb2[tid] = eb2[tid]; snb[tid] = nb[tid]; }
    __syncthreads();

    int idx = blockIdx.x * 256 + tid;
    float x[16];
#pragma unroll
    for (int j = 0; j < 16; j++) x[j] = Xm[(size_t)idx * 16 + j];

    float send[16], recv[16];
#pragma unroll
    for (int i = 0; i < 16; i++) {
        float s = 0.f, r = 0.f;
#pragma unroll
        for (int j = 0; j < 16; j++) { s += x[j] * sA[i * 16 + j]; r += x[j] * sA[j * 16 + i]; }
        send[i] = s; recv[i] = r;
    }
    float h1[16];
#pragma unroll
    for (int i = 0; i < 16; i++) {
        float s = sb1[i];
#pragma unroll
        for (int j = 0; j < 16; j++)
            s += send[j] * sw1[i * 32 + j] + recv[j] * sw1[i * 32 + 16 + j];
        h1[i] = fmaxf(s, 0.f);
    }
    float h2[16];
#pragma unroll
    for (int i = 0; i < 16; i++) {
        float s = sb2[i];
#pragma unroll
        for (int j = 0; j < 16; j++) s += h1[j] * sw2[i * 16 + j];
        h2[i] = fmaxf(s, 0.f);
    }
#pragma unroll
    for (int i = 0; i < 16; i++) {
        float s = snb[i];
#pragma unroll
        for (int j = 0; j < 16; j++)
            s += x[j] * snw[i * 32 + j] + h2[j] * snw[i * 32 + 16 + j];
        g_Z[(size_t)idx * 16 + i] = fmaxf(s, 0.f);
    }
}

// =====================================================================
// kernel 2: adstock + hill; g_xin = hill + Z
// =====================================================================
__global__ void __launch_bounds__(256)
adstock_kernel(const float* __restrict__ Xm, const float* __restrict__ alpha,
               const float* __restrict__ hill_a, const float* __restrict__ hill_g) {
    int tid = blockIdx.x * blockDim.x + threadIdx.x;
    int b = tid >> 4, m = tid & 15;
    float a  = fminf(fmaxf(alpha[m], 0.0f), 1.0f);
    float ha = fminf(fmaxf(hill_a[m], 0.1f), 3.0f);
    float hg = fminf(fmaxf(hill_g[m], 0.1f), 2.0f);
    float hga = powf(hg, ha);

    const float* xm = Xm + (size_t)b * T_ * M_ + m;
    float* hil = g_hill + (size_t)b * T_ * M_ + m;
    float* xin = g_xin + (size_t)b * T_ * M_ + m;
    const float* zp = g_Z + (size_t)b * T_ * M_ + m;

    float prev = 0.f, cmax = -1e30f;
    for (int t = 0; t < T_; t++) {
        float cur = xm[t * M_] + a * prev;
        prev = cur;
        hil[t * M_] = cur;
        cmax = fmaxf(cmax, cur);
    }
    cmax = fmaxf(cmax, 1e-6f);
    float inv = 1.0f / cmax;
    for (int t = 0; t < T_; t++) {
        float xn = fmaxf(hil[t * M_] * inv, 0.0f);
        float num = powf(xn, ha);
        float h = num / (num + hga + 1e-8f);
        hil[t * M_] = h;
        xin[t * M_] = h + zp[t * M_];
    }
}

// =====================================================================
// kernel 3: gi precompute. gi[t][r][b] = W_ih[r,:] . x[b,t,:] + b_ih[r]
// =====================================================================
__global__ void __launch_bounds__(256)
gi_kernel(const float* __restrict__ Xc, const float* __restrict__ W_ih,
          const float* __restrict__ b_ih) {
    __shared__ float Wc[288 * 32];
    __shared__ float xt[128 * 36];
    __shared__ float bC[288];
    int t = blockIdx.x, rbase = blockIdx.y * 288, b0 = blockIdx.z * 128;
    int tid = threadIdx.x;

    for (int e = tid; e < 288 * 32; e += 256) Wc[e] = W_ih[rbase * 32 + e];
    for (int e = tid; e < 288; e += 256) bC[e] = b_ih[rbase + e];
    for (int e = tid; e < 128 * 32; e += 256) {
        int b = e >> 5, c = e & 31;
        float v = (c < 16) ? g_xin[((size_t)(b0 + b) * T_ + t) * 16 + c]
                           : Xc[((size_t)(b0 + b) * T_ + t) * 16 + (c - 16)];
        xt[b * 36 + c] = v;
    }
    __syncthreads();

    int b = tid & 127;
    int r00 = tid >> 7;
    const float* xrow = xt + b * 36;
    ulonglong2 x8[8];
#pragma unroll
    for (int i = 0; i < 8; i++) x8[i] = *(const ulonglong2*)(xrow + i * 4);

    float* gout = g_gi + ((size_t)t * 2304 + rbase) * 256 + b0 + b;
    for (int r = r00; r < 288; r += 2) {
        const float* wrow = Wc + r * 32;
        unsigned long long a = 0ull;
#pragma unroll
        for (int i = 0; i < 8; i++) {
            ulonglong2 w8 = *(const ulonglong2*)(wrow + i * 4);
            FMA2(a, w8.x, x8[i].x);
            FMA2(a, w8.y, x8[i].y);
        }
        gout[(size_t)r * 256] = usum_(a) + bC[r];
    }
}

// =====================================================================
// kernel 4: h0 broadcast + barrier reset
// =====================================================================
__global__ void __launch_bounds__(256)
hinit_kernel(const float* __restrict__ h0) {
    int idx = blockIdx.x * 256 + threadIdx.x;
    if (idx == 0) { g_arrive = 0u; g_release = 0u; }
    int j = idx % H_;
    g_hseq[idx] = h0[j];
}

// =====================================================================
// kernel 5: persistent GRU. 128 CTAs = 2 bt x 64 hs. 384 threads =
// 6 row-groups(6 rows) x 2 k-groups(32 cols per 64-chunk).
// =====================================================================
extern __shared__ float g_sm[];

__global__ void __launch_bounds__(GT_, 1)
gru_persist_kernel(const float* __restrict__ W_hh, const float* __restrict__ b_hh) {
    float* Ws  = g_sm + OFF_WS;
    float* bh  = g_sm + OFF_BH;
    float* hpv = g_sm + OFF_HPV;
    float* stA = g_sm + OFF_STA;
    float* stB = g_sm + OFF_STB;
    float* Pb  = g_sm + OFF_STA;    // partial overlay: 2 regions of 36*128

    const int tid = threadIdx.x;
    const int tx = tid & 31, wid = tid >> 5;    // 12 warps
    const int rg = wid % 6;          // row group 0..5
    const int kg = wid / 6;          // k group 0..1
    const int r0 = rg * RPW;
    const int bt = blockIdx.x >> 6;
    const int hs = blockIdx.x & 63;
    const int j0 = hs * HSL;
    const int b0 = bt * 128;

    // ---- load W_hh slice + bh ONCE ----
    for (int e = tid; e < SROWS * 768; e += GT_) {
        int r = e / 768, k = e - r * 768;
        int grow = (r < 12) ? (j0 + r) : (r < 24) ? (H_ + j0 + r - 12) : (2 * H_ + j0 + r - 24);
        Ws[e] = W_hh[(size_t)grow * H_ + k];
    }
    if (tid < SROWS) {
        int r = tid;
        int grow = (r < 12) ? (j0 + r) : (r < 24) ? (H_ + j0 + r - 12) : (2 * H_ + j0 + r - 24);
        bh[r] = b_hh[grow];
    }
    for (int e = tid; e < HSL * 128; e += GT_) {
        int j = e >> 7, b = e & 127;
        hpv[e] = g_hseq[(size_t)(b0 + b) * H_ + j0 + j];
    }
    __syncthreads();

    for (int t = 0; t < T_; t++) {
        const float* hp = g_hseq + (size_t)t * BH_;
        float* ho = g_hseq + (size_t)(t + 1) * BH_;

        // ---- stage h chunk 0 -> stA (2048 x 16B) ----
        for (int i = tid; i < 2048; i += GT_) {
            int b = i >> 4, kq = i & 15;
            CP_ASYNC16(stA + b * STP + kq * 4, hp + (size_t)(b0 + b) * H_ + kq * 4);
        }
        CP_COMMIT();

        unsigned long long acc[RPW][4];
#pragma unroll
        for (int r = 0; r < RPW; r++)
#pragma unroll
            for (int b = 0; b < 4; b++) acc[r][b] = 0ull;

        for (int c = 0; c < 12; c++) {
            CP_WAIT0();
            __syncthreads();
            float* cur = (c & 1) ? stB : stA;
            float* nxt = (c & 1) ? stA : stB;
            if (c < 11) {
                const float* base = hp + (size_t)b0 * H_ + (c + 1) * 64;
                for (int i = tid; i < 2048; i += GT_) {
                    int b = i >> 4, kq = i & 15;
                    CP_ASYNC16(nxt + b * STP + kq * 4, base + (size_t)b * H_ + kq * 4);
                }
                CP_COMMIT();
            }
            const float* hbase = cur + tx * STP + kg * 32;
            const float* wbase = Ws + r0 * 768 + c * 64 + kg * 32;
#pragma unroll
            for (int k4 = 0; k4 < 32; k4 += 4) {
                ulonglong2 h4[4];
#pragma unroll
                for (int bb = 0; bb < 4; bb++)
                    h4[bb] = *(const ulonglong2*)(hbase + bb * (32 * STP) + k4);
#pragma unroll
                for (int r = 0; r < RPW; r++) {
                    ulonglong2 w4 = *(const ulonglong2*)(wbase + r * 768 + k4);
#pragma unroll
                    for (int bb = 0; bb < 4; bb++) {
                        FMA2(acc[r][bb], w4.x, h4[bb].x);
                        FMA2(acc[r][bb], w4.y, h4[bb].y);
                    }
                }
            }
        }
        __syncthreads();   // all reads done before partial overlay writes

        // ---- write split-k partials (region per kg), one sync ----
        float* myP = Pb + kg * 4608;
#pragma unroll
        for (int r = 0; r < RPW; r++)
#pragma unroll
            for (int bb = 0; bb < 4; bb++)
                myP[(r0 + r) * 128 + tx + 32 * bb] = usum_(acc[r][bb]);
        __syncthreads();

        // ---- epilogue: gates + state update ----
        const float* gi_t = g_gi + (size_t)t * 2304 * 256;
        for (int e = tid; e < HSL * 128; e += GT_) {
            int j = e >> 7, b = e & 127;
            int o = j * 128 + b;
            float hr = Pb[o] + Pb[4608 + o];
            int oz = (12 + j) * 128 + b;
            float hz = Pb[oz] + Pb[4608 + oz];
            int on = (24 + j) * 128 + b;
            float hn = Pb[on] + Pb[4608 + on];
            float gr = gi_t[(size_t)(j0 + j) * 256 + b0 + b];
            float gz = gi_t[(size_t)(768 + j0 + j) * 256 + b0 + b];
            float gn = gi_t[(size_t)(1536 + j0 + j) * 256 + b0 + b];
            float rg_ = sigmoidf_(gr + hr + bh[j]);
            float zg  = sigmoidf_(gz + hz + bh[12 + j]);
            float nn  = tanhf(gn + rg_ * (hn + bh[24 + j]));
            float hv  = hpv[e];
            float hnew = (1.f - zg) * nn + zg * hv;
            hpv[e] = hnew;
            ho[(size_t)(b0 + b) * H_ + j0 + j] = hnew;
        }

        // ---- grid barrier ----
        if (t < T_ - 1) {
            __threadfence();
            __syncthreads();
            if (tid == 0) {
                unsigned tgt = (unsigned)t + 1u;
                if (atomicAdd(&g_arrive, 1u) == 127u) {
                    g_arrive = 0u;
                    __threadfence();
                    *(volatile unsigned*)&g_release = tgt;
                } else {
                    while (*(volatile unsigned*)&g_release < tgt) { __nanosleep(32); }
                }
                __threadfence();
            }
            __syncthreads();
        }
    }
}

// =====================================================================
// kernel 6: heads
// =====================================================================
__global__ void __launch_bounds__(256, 1)
heads_kernel(const float* __restrict__ Xc,
             const float* __restrict__ wraw_w, const float* __restrict__ wraw_b,
             const float* __restrict__ ctrl_w, const float* __restrict__ ctrl_b,
             const float* __restrict__ reg_emb, const float* __restrict__ bias,
             float* __restrict__ out_y, float* __restrict__ out_w, float* __restrict__ out_c) {
    extern __shared__ float hsm[];
    float* sww = hsm;
    float* scw = sww + 12288;
    float* scb = scw + 12288;
    float* srg = scb + 768;
    float* swb = srg + 768;
    int tid = threadIdx.x;
    for (int e = tid; e < 12288; e += 256) { sww[e] = wraw_w[e]; scw[e] = ctrl_w[e]; }
    for (int e = tid; e < 768; e += 256) { scb[e] = ctrl_b[e]; srg[e] = reg_emb[e]; }
    if (tid < 16) swb[tid] = wraw_b[tid];
    __syncthreads();

    int wid = tid >> 5, lane = tid & 31;
    float bias0 = bias[0];

    float rp = 0.f;
#pragma unroll
    for (int i = 0; i < 24; i++) rp += srg[lane + 32 * i];
    rp = wredux(rp) * 0.3f;

    for (int it = 0; it < 8; it++) {
        int n = blockIdx.x * 64 + wid * 8 + it;
        int b = n >> 9, t = n & 511;

        const float* hrow = g_hseq + (size_t)(t + 1) * BH_ + (size_t)b * H_;
        float hv[24];
#pragma unroll
        for (int i = 0; i < 24; i++) hv[i] = hrow[lane + 32 * i];
        float wp[16];
#pragma unroll
        for (int m = 0; m < 16; m++) {
            float p = 0.f;
#pragma unroll
            for (int i = 0; i < 24; i++) p += hv[i] * sww[m * 768 + lane + 32 * i];
            p = wredux(p);
            wp[m] = softplusf_(p + swb[m]);
        }
        if (t == 0) {
            const float* h2 = g_hseq + (size_t)2 * BH_ + (size_t)b * H_;
            float h2v[24];
#pragma unroll
            for (int i = 0; i < 24; i++) h2v[i] = h2[lane + 32 * i];
#pragma unroll
            for (int m = 0; m < 16; m++) {
                float p = 0.f;
#pragma unroll
                for (int i = 0; i < 24; i++) p += h2v[i] * sww[m * 768 + lane + 32 * i];
                p = wredux(p);
                wp[m] = 0.5f * softplusf_(p + swb[m]) + 0.5f * wp[m];
            }
        }

        float media = 0.f;
        const float* hillrow = g_hill + ((size_t)b * T_ + t) * M_;
        float cb[16];
#pragma unroll
        for (int m = 0; m < 16; m++) { cb[m] = hillrow[m] * wp[m]; media += cb[m]; }

        float xc[16];
#pragma unroll
        for (int c = 0; c < 16; c++) xc[c] = Xc[((size_t)b * T_ + t) * C_ + c];
        float ct = 0.f;
#pragma unroll
        for (int i = 0; i < 24; i++) {
            int j = lane + 32 * i;
            float s = scb[j];
#pragma unroll
            for (int c = 0; c < 16; c++) s += xc[c] * scw[j * 16 + c];
            ct += fmaxf(s, 0.f);
        }
        ct = wredux(ct) * 0.3f;

        float y = media + ct + rp + bias0;
        if (lane == 0) out_y[(size_t)b * T_ + t] = y;
        if (out_w && lane < 16) out_w[((size_t)b * T_ + t) * M_ + lane] = wp[lane];
        if (out_c && lane < 16) out_c[((size_t)b * T_ + t) * M_ + lane] = cb[lane];
    }
}

// =====================================================================
// launch
// =====================================================================
extern "C" void kernel_launch(void* const* d_in, const int* in_sizes, int n_in,
                              void* d_out, int out_size) {
    const float* Xm     = (const float*)d_in[0];
    const float* Xc     = (const float*)d_in[1];
    const float* A      = (const float*)d_in[3];
    const float* ew1    = (const float*)d_in[4];
    const float* eb1    = (const float*)d_in[5];
    const float* ew2    = (const float*)d_in[6];
    const float* eb2    = (const float*)d_in[7];
    const float* nw     = (const float*)d_in[8];
    const float* nb     = (const float*)d_in[9];
    const float* W_ih   = (const float*)d_in[10];
    const float* W_hh   = (const float*)d_in[11];
    const float* b_ih   = (const float*)d_in[12];
    const float* b_hh   = (const float*)d_in[13];
    const float* wraw_w = (const float*)d_in[14];
    const float* wraw_b = (const float*)d_in[15];
    const float* alpha  = (const float*)d_in[16];
    const float* hill_a = (const float*)d_in[17];
    const float* hill_g = (const float*)d_in[18];
    const float* ctrl_w = (const float*)d_in[19];
    const float* ctrl_b = (const float*)d_in[20];
    const float* regemb = (const float*)d_in[21];
    const float* bias   = (const float*)d_in[22];
    const float* h0     = (const float*)d_in[23];

    const int GRU_SMEM  = SM_FLOATS * 4;                                 // 186528
    const int HEAD_SMEM = (12288 + 12288 + 768 + 768 + 16) * 4;          // 104512
    cudaFuncSetAttribute(gru_persist_kernel, cudaFuncAttributeMaxDynamicSharedMemorySize, GRU_SMEM);
    cudaFuncSetAttribute(heads_kernel, cudaFuncAttributeMaxDynamicSharedMemorySize, HEAD_SMEM);

    enc_kernel<<<BT_ / 256, 256>>>(Xm, A, ew1, eb1, ew2, eb2, nw, nb);
    adstock_kernel<<<(B_ * M_) / 256, 256>>>(Xm, alpha, hill_a, hill_g);
    gi_kernel<<<dim3(T_, 8, 2), 256>>>(Xc, W_ih, b_ih);
    hinit_kernel<<<BH_ / 256, 256>>>(h0);

    gru_persist_kernel<<<128, GT_, GRU_SMEM>>>(W_hh, b_hh);

    float* out = (float*)d_out;
    float* oy = out;
    float* ow = nullptr;
    float* oc = nullptr;
    if (out_size >= BT_ + 2 * BTM_) { ow = out + BT_; oc = out + BT_ + BTM_; }
    else if (out_size >= BT_ + BTM_) { ow = out + BT_; }

    heads_kernel<<<BT_ / 64, 256, HEAD_SMEM>>>(Xc, wraw_w, wraw_b, ctrl_w, ctrl_b,
                                               regemb, bias, oy, ow, oc);
}